// round 13
// baseline (speedup 1.0000x reference)
#include <cuda_runtime.h>
#include <cuda_fp16.h>
#include <cstdint>

#define OUT_DIM 8192
#define IN_DIM  8192
#define NGRP    64                  /* scale groups per output row (GS=128) */
#define O_CTA   32                  /* o-rows per CTA */
#define STAGE_K 128                 /* K elts per stage = one scale group = 512B/row */
#define NSTAGES (IN_DIM / STAGE_K)  /* 64 */
#define RING    5
#define ROW_STRIDE 576              /* 512+64: ≡64 mod 128 -> conflict-free LDS.128 */
#define STAGE_PAD (O_CTA * ROW_STRIDE)      /* 18432 B */
#define STAGE_TX  (O_CTA * 512)             /* 16384 B */
#define SMEM_BYTES (RING * STAGE_PAD)       /* 92160 B -> 2 CTAs/SM */

// x pre-packed per (kstep, lane): 2 uint4 = fragments for all 4 ntiles.
// k PERMUTED inside each 16-wide kstep: fragment positions (2tig,2tig+1,2tig+8,
// 2tig+9) hold physical k (4tig..4tig+3); A reads raw consecutive ints.
__device__ uint4 g_xfrag[512 * 32 * 2];

__global__ void xconv_kernel(const float* __restrict__ x) {
    const int idx  = blockIdx.x * blockDim.x + threadIdx.x;   // 0..32767
    const int lane = idx & 31;
    const int h    = (idx >> 5) & 1;          // which uint4 (ntile pair)
    const int kt   = idx >> 6;
    const int g    = lane >> 2;
    const int tig  = lane & 3;
    const int k0   = kt * 16 + tig * 4;

    unsigned w[4];
    #pragma unroll
    for (int p = 0; p < 2; p++) {
        const int n = (h * 2 + p) * 8 + g;
        const float4 a = *reinterpret_cast<const float4*>(x + n * IN_DIM + k0);
        __half2 lo = __floats2half2_rn(a.x, a.y);
        __half2 hi = __floats2half2_rn(a.z, a.w);
        w[p * 2]     = *reinterpret_cast<unsigned*>(&lo);
        w[p * 2 + 1] = *reinterpret_cast<unsigned*>(&hi);
    }
    g_xfrag[(kt * 32 + lane) * 2 + h] = make_uint4(w[0], w[1], w[2], w[3]);
}

// t in {-1,0,1}: low 16 bits of (t<<14) are exactly fp16(2t); scale by s/2.
__device__ __forceinline__ unsigned cvt_pair(unsigned t0, unsigned t1, unsigned sh2) {
    unsigned u0 = t0 << 14;
    unsigned u1 = t1 << 14;
    unsigned p;
    asm("prmt.b32 %0, %1, %2, 0x5410;" : "=r"(p) : "r"(u0), "r"(u1));
    asm("mul.rn.f16x2 %0, %1, %2;" : "=r"(p) : "r"(p), "r"(sh2));
    return p;
}

__device__ __forceinline__ void mma16816(float c[4], unsigned a0, unsigned a1,
                                         unsigned a2, unsigned a3,
                                         unsigned b0, unsigned b1) {
    asm("mma.sync.aligned.m16n8k16.row.col.f32.f16.f16.f32 "
        "{%0,%1,%2,%3}, {%4,%5,%6,%7}, {%8,%9}, {%0,%1,%2,%3};"
        : "+f"(c[0]), "+f"(c[1]), "+f"(c[2]), "+f"(c[3])
        : "r"(a0), "r"(a1), "r"(a2), "r"(a3), "r"(b0), "r"(b1));
}

__device__ __forceinline__ unsigned smem_u32(const void* p) {
    unsigned a;
    asm("{ .reg .u64 t; cvta.to.shared.u64 t, %1; cvt.u32.u64 %0, t; }"
        : "=r"(a) : "l"(p));
    return a;
}
__device__ __forceinline__ void mbar_init(unsigned addr, unsigned cnt) {
    asm volatile("mbarrier.init.shared.b64 [%0], %1;" :: "r"(addr), "r"(cnt) : "memory");
}
__device__ __forceinline__ void mbar_arrive(unsigned addr) {
    asm volatile("mbarrier.arrive.release.cta.shared::cta.b64 _, [%0];"
                 :: "r"(addr) : "memory");
}
__device__ __forceinline__ void mbar_arrive_expect_tx(unsigned addr, unsigned bytes) {
    asm volatile("mbarrier.arrive.expect_tx.shared.b64 _, [%0], %1;"
                 :: "r"(addr), "r"(bytes) : "memory");
}
__device__ __forceinline__ void mbar_wait(unsigned addr, unsigned parity) {
    asm volatile(
        "{\n\t.reg .pred P;\n"
        "W%=:\n\t"
        "mbarrier.try_wait.parity.acquire.cta.shared::cta.b64 P, [%0], %1, 0x989680;\n\t"
        "@P bra D%=;\n\t"
        "bra W%=;\n"
        "D%=:\n\t}"
        :: "r"(addr), "r"(parity) : "memory");
}
__device__ __forceinline__ void bulk_g2s(unsigned dst, const void* src,
                                         unsigned bytes, unsigned mbar) {
    asm volatile(
        "cp.async.bulk.shared::cluster.global.mbarrier::complete_tx::bytes "
        "[%0], [%1], %2, [%3];"
        :: "r"(dst), "l"(src), "r"(bytes), "r"(mbar) : "memory");
}

extern "C" __global__ void __launch_bounds__(288, 2)
tmma_kernel(const int* __restrict__ tern,
            const float* __restrict__ scales,
            float* __restrict__ out)
{
    extern __shared__ char sm[];                 // [RING][32 rows][576 B]
    __shared__ unsigned long long mbar_store[2 * RING];

    const int tid  = threadIdx.x;
    const int lane = tid & 31;
    const int kg   = tid >> 5;                   // 0..7 consumers, 8 producer
    const int g    = lane >> 2;
    const int tig  = lane & 3;
    const int o_tile = blockIdx.x * O_CTA;

    const unsigned ring_b = smem_u32(sm);
    unsigned full_b[RING], empty_b[RING];
    #pragma unroll
    for (int p = 0; p < RING; p++) {
        full_b[p]  = smem_u32(&mbar_store[p]);
        empty_b[p] = smem_u32(&mbar_store[RING + p]);
    }

    if (tid == 0) {
        #pragma unroll
        for (int p = 0; p < RING; p++) {
            mbar_init(full_b[p], 1);             // expect_tx arrival (lane 0)
            mbar_init(empty_b[p], 8);            // one elected lane per consumer warp
        }
    }
    __syncthreads();

    if (kg == 8) {
        // ── Producer warp: lane r streams row o_tile+r. Ring backpressure only.
        // Producer phase starts at 1: first RING empty-waits pass immediately
        // (wait(P) blocks only while the barrier's parity bit == P; init bit 0).
        const char* src = reinterpret_cast<const char*>(
            tern + (long)(o_tile + lane) * IN_DIM);
        const unsigned dst = ring_b + lane * ROW_STRIDE;
        for (int j = 0; j < NSTAGES; j++) {
            const int slot = j % RING;
            mbar_wait(empty_b[slot], 1 ^ ((j / RING) & 1));
            if (lane == 0) mbar_arrive_expect_tx(full_b[slot], STAGE_TX);
            __syncwarp();
            bulk_g2s(dst + slot * STAGE_PAD, src + j * 512, 512, full_b[slot]);
        }
    } else {
        // ── Consumer warps: warp kg consumes kstep kg of each stage.
        float acc[2][4][4];
        #pragma unroll
        for (int m = 0; m < 2; m++)
            #pragma unroll
            for (int n = 0; n < 4; n++)
                #pragma unroll
                for (int i = 0; i < 4; i++) acc[m][n][i] = 0.f;

        uint4 bcur0 = g_xfrag[(kg * 32 + lane) * 2];
        uint4 bcur1 = g_xfrag[(kg * 32 + lane) * 2 + 1];

        for (int i = 0; i < NSTAGES; i++) {
            const int slot = i % RING;

            uint4 bn0, bn1;
            if (i + 1 < NSTAGES) {
                const int kglob = (i + 1) * 8 + kg;
                bn0 = g_xfrag[(kglob * 32 + lane) * 2];
                bn1 = g_xfrag[(kglob * 32 + lane) * 2 + 1];
            }
            unsigned sh[4];
            #pragma unroll
            for (int s = 0; s < 4; s++) {        // stage == scale group i
                const float sc = __ldg(scales + (o_tile + s * 8 + g) * NGRP + i) * 0.5f;
                const __half2 p = __half2half2(__float2half_rn(sc));
                sh[s] = *reinterpret_cast<const unsigned*>(&p);
            }

            mbar_wait(full_b[slot], (i / RING) & 1);

            const int koff = kg * 64 + tig * 16;
            #pragma unroll
            for (int m = 0; m < 2; m++) {
                const int4 v0 = *reinterpret_cast<const int4*>(
                    sm + slot * STAGE_PAD + (m * 16 + g) * ROW_STRIDE + koff);
                const int4 v1 = *reinterpret_cast<const int4*>(
                    sm + slot * STAGE_PAD + (m * 16 + 8 + g) * ROW_STRIDE + koff);
                const unsigned a0 = cvt_pair((unsigned)v0.x, (unsigned)v0.y, sh[m * 2]);
                const unsigned a2 = cvt_pair((unsigned)v0.z, (unsigned)v0.w, sh[m * 2]);
                const unsigned a1 = cvt_pair((unsigned)v1.x, (unsigned)v1.y, sh[m * 2 + 1]);
                const unsigned a3 = cvt_pair((unsigned)v1.z, (unsigned)v1.w, sh[m * 2 + 1]);
                mma16816(acc[m][0], a0, a1, a2, a3, bcur0.x, bcur0.y);
                mma16816(acc[m][1], a0, a1, a2, a3, bcur0.z, bcur0.w);
                mma16816(acc[m][2], a0, a1, a2, a3, bcur1.x, bcur1.y);
                mma16816(acc[m][3], a0, a1, a2, a3, bcur1.z, bcur1.w);
            }

            // Release this slot back to the producer (one arrival per warp).
            __syncwarp();
            if (lane == 0) mbar_arrive(empty_b[slot]);

            bcur0 = bn0;
            bcur1 = bn1;
        }

        // Deterministic cross-warp K reduction; ring smem reused as the buffer.
        __syncthreads();                         // producer joins below
        float* red = reinterpret_cast<float*>(sm);
        #pragma unroll
        for (int m = 0; m < 2; m++)
            #pragma unroll
            for (int nt = 0; nt < 4; nt++)
                #pragma unroll
                for (int i = 0; i < 4; i++)
                    red[(kg * 32 + lane) * 32 + m * 16 + nt * 4 + i] = acc[m][nt][i];
        __syncthreads();

        #pragma unroll
        for (int jj = 0; jj < 4; jj++) {
            const int j = kg * 4 + jj;
            float s = red[lane * 32 + j];
            #pragma unroll
            for (int w = 1; w < 8; w++)
                s += red[(w * 32 + lane) * 32 + j];
            const int m  = j >> 4;
            const int nt = (j >> 2) & 3;
            const int i  = j & 3;
            const int row = o_tile + m * 16 + ((i & 2) ? 8 : 0) + g;
            const int t   = nt * 8 + tig * 2 + (i & 1);
            out[(long)t * OUT_DIM + row] = s;
        }
    }

    // Producer hits the two barriers of the reduction epilogue.
    if (kg == 8) {
        __syncthreads();
        __syncthreads();
    }
}

extern "C" void kernel_launch(void* const* d_in, const int* in_sizes, int n_in,
                              void* d_out, int out_size) {
    const float* x      = (const float*)d_in[0];
    const int*   tern   = (const int*)d_in[1];
    const float* scales = (const float*)d_in[2];
    float*       out    = (float*)d_out;

    cudaFuncSetAttribute(tmma_kernel,
                         cudaFuncAttributeMaxDynamicSharedMemorySize, SMEM_BYTES);
    xconv_kernel<<<128, 256>>>(x);
    tmma_kernel<<<OUT_DIM / O_CTA, 288, SMEM_BYTES>>>(tern, scales, out);
}

// round 15
// speedup vs baseline: 1.8813x; 1.8813x over previous
#include <cuda_runtime.h>
#include <cuda_fp16.h>
#include <cstdint>

#define OUT_DIM 8192
#define IN_DIM  8192
#define NGRP    64                 /* scale groups per output row (GS=128) */
#define KSTEPS  512                /* IN_DIM / 16 */
#define KSPLIT  8                  /* K split across the 8 warps of a CTA */
#define KS_W    (KSTEPS / KSPLIT)  /* 64 ksteps per warp */
#define O_CTA   32                 /* o-rows per CTA (per warp: all 32) */
#define DEPTH_S 6                  /* cp.async smem ring stages (A) */
#define DEPTH_B 4                  /* B register prefetch depth (L2-resident) */
#define STAGE_I4 128               /* int4 per ring stage per warp (4 streams x 32 lanes) */
#define RING_BYTES (KSPLIT * DEPTH_S * 2048)   /* 96 KB */

// x pre-packed per (kstep, lane): 2 uint4 = fragments for all 4 ntiles.
// k is PERMUTED inside each 16-wide kstep: fragment positions
// (2tig, 2tig+1, 2tig+8, 2tig+9) hold physical k (4tig..4tig+3).
// A uses the same permutation, so the MMA result is unchanged.
__device__ uint4 g_xfrag[KSTEPS * 32 * 2];

// Fast variant (validated in R13): 32768 threads, one uint4 each.
__global__ void xconv_kernel(const float* __restrict__ x) {
    const int idx  = blockIdx.x * blockDim.x + threadIdx.x;   // 0..32767
    const int lane = idx & 31;
    const int h    = (idx >> 5) & 1;          // which uint4 (ntile pair)
    const int kt   = idx >> 6;
    const int g    = lane >> 2;
    const int tig  = lane & 3;
    const int k0   = kt * 16 + tig * 4;

    unsigned w[4];
    #pragma unroll
    for (int p = 0; p < 2; p++) {
        const int n = (h * 2 + p) * 8 + g;
        const float4 a = *reinterpret_cast<const float4*>(x + n * IN_DIM + k0);
        __half2 lo = __floats2half2_rn(a.x, a.y);
        __half2 hi = __floats2half2_rn(a.z, a.w);
        w[p * 2]     = *reinterpret_cast<unsigned*>(&lo);
        w[p * 2 + 1] = *reinterpret_cast<unsigned*>(&hi);
    }
    g_xfrag[(kt * 32 + lane) * 2 + h] = make_uint4(w[0], w[1], w[2], w[3]);
}

// t in {-1,0,1}: low 16 bits of (t<<14) are exactly fp16(2t). Pack a pair, then
// scale by half2(s/2): products are +-fp16(s), exact (x2 only shifts the exponent).
__device__ __forceinline__ unsigned cvt_pair(unsigned t0, unsigned t1, unsigned sh2) {
    unsigned u0 = t0 << 14;
    unsigned u1 = t1 << 14;
    unsigned p;
    asm("prmt.b32 %0, %1, %2, 0x5410;" : "=r"(p) : "r"(u0), "r"(u1));
    asm("mul.rn.f16x2 %0, %1, %2;" : "=r"(p) : "r"(p), "r"(sh2));
    return p;
}

__device__ __forceinline__ void mma16816(float c[4], unsigned a0, unsigned a1,
                                         unsigned a2, unsigned a3,
                                         unsigned b0, unsigned b1) {
    asm("mma.sync.aligned.m16n8k16.row.col.f32.f16.f16.f32 "
        "{%0,%1,%2,%3}, {%4,%5,%6,%7}, {%8,%9}, {%0,%1,%2,%3};"
        : "+f"(c[0]), "+f"(c[1]), "+f"(c[2]), "+f"(c[3])
        : "r"(a0), "r"(a1), "r"(a2), "r"(a3), "r"(b0), "r"(b1));
}

__device__ __forceinline__ unsigned smem_u32(const void* p) {
    unsigned a;
    asm("{ .reg .u64 t; cvta.to.shared.u64 t, %1; cvt.u32.u64 %0, t; }"
        : "=r"(a) : "l"(p));
    return a;
}
#define CP_ASYNC16(dst, src) \
    asm volatile("cp.async.cg.shared.global [%0], [%1], 16;" \
                 :: "r"(dst), "l"(src) : "memory")
#define CP_COMMIT() asm volatile("cp.async.commit_group;" ::: "memory")
#define CP_WAIT(n)  asm volatile("cp.async.wait_group %0;" :: "n"(n) : "memory")

extern "C" __global__ void __launch_bounds__(256, 2)
tmma_kernel(const int* __restrict__ tern,
            const float* __restrict__ scales,
            float* __restrict__ out)
{
    extern __shared__ char sm[];   // [KSPLIT][DEPTH_S][4 streams][32 lanes] int4 ring

    const int lane = threadIdx.x & 31;
    const int kg   = threadIdx.x >> 5;       // warp = K eighth (0..7)
    const int g    = lane >> 2;
    const int tig  = lane & 3;
    const int o_tile = blockIdx.x * O_CTA;   // CTA: 32 o-rows x all 32 t x full K
    const int kbase = kg * KS_W;

    // 4 A row-streams: rows o_tile + s*8 + g  (tiles: (s0,s1) and (s2,s3)).
    const int4* pA[4];
    #pragma unroll
    for (int s = 0; s < 4; s++)
        pA[s] = reinterpret_cast<const int4*>(
            tern + (long)(o_tile + s * 8 + g) * IN_DIM + kbase * 16 + tig * 4);
    const uint4* pB = g_xfrag + (long)(kbase * 32 + lane) * 2;

    // Lane-local smem slots (cp.async dst == this lane's LDS src).
    const unsigned ring0 = smem_u32(sm) + kg * (DEPTH_S * 2048) + lane * 16;
    const int4* ringp = reinterpret_cast<const int4*>(sm) + kg * (DEPTH_S * STAGE_I4) + lane;

    float acc[2][4][4];                      // [m-tile][ntile][frag]
    #pragma unroll
    for (int m = 0; m < 2; m++)
        #pragma unroll
        for (int n = 0; n < 4; n++)
            #pragma unroll
            for (int i = 0; i < 4; i++) acc[m][n][i] = 0.f;

    uint4 bbuf[DEPTH_B][2];

    // Prologue: fill A ring and B register pipe.
    #pragma unroll
    for (int d = 0; d < DEPTH_S; d++) {
        #pragma unroll
        for (int s = 0; s < 4; s++)
            CP_ASYNC16(ring0 + d * 2048 + s * 512, pA[s] + d * 4);
        CP_COMMIT();
    }
    #pragma unroll
    for (int d = 0; d < DEPTH_B; d++) {
        bbuf[d][0] = pB[d * 64];
        bbuf[d][1] = pB[d * 64 + 1];
    }

    unsigned sh[4] = {0, 0, 0, 0};

    #pragma unroll 4
    for (int ks = 0; ks < KS_W; ks++) {
        if ((ks & 7) == 0) {                 // new scale group (GS=128 = 8 ksteps)
            const int grp = (kbase + ks) >> 3;
            #pragma unroll
            for (int s = 0; s < 4; s++) {
                const float sc = __ldg(scales + (o_tile + s * 8 + g) * NGRP + grp) * 0.5f;
                const __half2 p = __half2half2(__float2half_rn(sc));
                sh[s] = *reinterpret_cast<const unsigned*>(&p);
            }
        }

        const int st = ks % DEPTH_S;
        const int ib = ks & (DEPTH_B - 1);

        CP_WAIT(DEPTH_S - 1);                // oldest stage resident

        int4 va[4];
        #pragma unroll
        for (int s = 0; s < 4; s++)
            va[s] = ringp[st * STAGE_I4 + s * 32];      // LDS.128, lane-local
        const uint4 vb0 = bbuf[ib][0];
        const uint4 vb1 = bbuf[ib][1];

        // Refill (dummy commits keep FIFO arithmetic uniform at the tail).
        const int ka = ks + DEPTH_S;
        if (ka < KS_W) {
            #pragma unroll
            for (int s = 0; s < 4; s++)
                CP_ASYNC16(ring0 + st * 2048 + s * 512, pA[s] + ka * 4);
        }
        CP_COMMIT();
        const int kb = ks + DEPTH_B;
        if (kb < KS_W) {
            bbuf[ib][0] = pB[kb * 64];
            bbuf[ib][1] = pB[kb * 64 + 1];
        }

        #pragma unroll
        for (int m = 0; m < 2; m++) {
            const int4 v0 = va[m * 2];
            const int4 v1 = va[m * 2 + 1];
            const unsigned a0 = cvt_pair((unsigned)v0.x, (unsigned)v0.y, sh[m * 2]);
            const unsigned a2 = cvt_pair((unsigned)v0.z, (unsigned)v0.w, sh[m * 2]);
            const unsigned a1 = cvt_pair((unsigned)v1.x, (unsigned)v1.y, sh[m * 2 + 1]);
            const unsigned a3 = cvt_pair((unsigned)v1.z, (unsigned)v1.w, sh[m * 2 + 1]);
            mma16816(acc[m][0], a0, a1, a2, a3, vb0.x, vb0.y);
            mma16816(acc[m][1], a0, a1, a2, a3, vb0.z, vb0.w);
            mma16816(acc[m][2], a0, a1, a2, a3, vb1.x, vb1.y);
            mma16816(acc[m][3], a0, a1, a2, a3, vb1.z, vb1.w);
        }
    }

    // Deterministic cross-warp K reduction; ring smem reused as the buffer.
    CP_WAIT(0);
    __syncthreads();
    float* red = reinterpret_cast<float*>(sm);          // [KSPLIT][32][32]
    #pragma unroll
    for (int m = 0; m < 2; m++)
        #pragma unroll
        for (int nt = 0; nt < 4; nt++)
            #pragma unroll
            for (int i = 0; i < 4; i++)
                red[(kg * 32 + lane) * 32 + m * 16 + nt * 4 + i] = acc[m][nt][i];
    __syncthreads();

    // Warp kg sums j in [kg*4, kg*4+4) over all 8 warps in fixed order.
    #pragma unroll
    for (int jj = 0; jj < 4; jj++) {
        const int j = kg * 4 + jj;
        float s = red[lane * 32 + j];                   // w = 0
        #pragma unroll
        for (int w = 1; w < KSPLIT; w++)
            s += red[(w * 32 + lane) * 32 + j];
        const int m  = j >> 4;
        const int nt = (j >> 2) & 3;
        const int i  = j & 3;
        const int row = o_tile + m * 16 + ((i & 2) ? 8 : 0) + g;
        const int t   = nt * 8 + tig * 2 + (i & 1);
        out[(long)t * OUT_DIM + row] = s;
    }
}

extern "C" void kernel_launch(void* const* d_in, const int* in_sizes, int n_in,
                              void* d_out, int out_size) {
    const float* x      = (const float*)d_in[0];
    const int*   tern   = (const int*)d_in[1];
    const float* scales = (const float*)d_in[2];
    float*       out    = (float*)d_out;

    cudaFuncSetAttribute(tmma_kernel,
                         cudaFuncAttributeMaxDynamicSharedMemorySize, RING_BYTES);
    xconv_kernel<<<128, 256>>>(x);
    tmma_kernel<<<OUT_DIM / O_CTA, 256, RING_BYTES>>>(tern, scales, out);
}